// round 8
// baseline (speedup 1.0000x reference)
#include <cuda_runtime.h>
#include <cuda_bf16.h>
#include <math.h>
#include <stdint.h>

// Shape (fixed by dataset): N=65536, P=2048, D=64, 10 classes.
#define NPTS 65536
#define PPTS 2048
#define DDIM 64
#define BM 128
#define BN 128
#define NTHREADS 512
#define LDSS 72              // bf16 per smem row (64 + 8 pad): conflict-free ldmatrix
#define ROWB (LDSS * 2)      // 144 bytes per padded row
#define NTILES (PPTS / BN)   // 16
#define NBLOCKS (NPTS / BM)  // 512

// __device__ scratch (allocation-free rule). Only prototypes staged.
__device__ __align__(16) __nv_bfloat16 g_pb[PPTS * DDIM];
__device__ __align__(16) float g_p2[PPTS];
__device__ float g_partial[NBLOCKS];
__device__ unsigned int g_count;   // zero-init; last block resets

// Dynamic smem layout (bytes)
#define SM_B0    0                 // B tile buffer (even t)         18432
#define SM_AB1   18432             // A tile, then B buffer (odd t)  18432
#define SM_PP2   36864             // 2 bufs x 128 f32                1024
#define SM_PPL   37888             // 2 bufs x 128 i32                1024
#define SM_RED   38912             // [2 wn][2][128] f32              4096
#define SM_XS2   43008             // 128 f32 row norms                512
#define SM_RSUM  43520             // 16 f32
#define SM_FLAG  43584
#define SM_TOTAL 43648

__device__ __forceinline__ void cp16(uint32_t dst, const void* src) {
    asm volatile("cp.async.cg.shared.global [%0], [%1], 16;\n" :: "r"(dst), "l"(src));
}
#define CP_COMMIT() asm volatile("cp.async.commit_group;\n" ::: "memory")
#define CP_WAIT(n)  asm volatile("cp.async.wait_group %0;\n" :: "n"(n) : "memory")

__device__ __forceinline__ uint32_t padoff(int idx) {     // idx-th 16B chunk
    return (uint32_t)((idx >> 3) * ROWB + (idx & 7) * 16);
}
__device__ __forceinline__ uint32_t pk2(float a, float b) {
    __nv_bfloat162 t = __floats2bfloat162_rn(a, b);
    return *(uint32_t*)&t;
}
#define LDSMX4(rr, addr) asm volatile( \
    "ldmatrix.sync.aligned.m8n8.x4.shared.b16 {%0,%1,%2,%3}, [%4];\n" \
    : "=r"((rr)[0]), "=r"((rr)[1]), "=r"((rr)[2]), "=r"((rr)[3]) : "r"(addr))
#define MMA16816(cc, aa, b0, b1) asm volatile( \
    "mma.sync.aligned.m16n8k16.row.col.f32.bf16.bf16.f32 " \
    "{%0,%1,%2,%3}, {%4,%5,%6,%7}, {%8,%9}, {%0,%1,%2,%3};\n" \
    : "+f"((cc)[0]), "+f"((cc)[1]), "+f"((cc)[2]), "+f"((cc)[3]) \
    : "r"((aa)[0]), "r"((aa)[1]), "r"((aa)[2]), "r"((aa)[3]), "r"(b0), "r"(b1))

// ---------------------------------------------------------------------------
// Prep (prototypes only): fp32 rows -> bf16 rows + row sum-of-squares.
// ---------------------------------------------------------------------------
__global__ void prep_proto(const float* __restrict__ p) {
    int w = (blockIdx.x * blockDim.x + threadIdx.x) >> 5;
    int lane = threadIdx.x & 31;
    if (w >= PPTS) return;
    float2 v = ((const float2*)(p + (size_t)w * DDIM))[lane];
    float ss = v.x * v.x + v.y * v.y;
    #pragma unroll
    for (int o = 16; o; o >>= 1) ss += __shfl_xor_sync(0xffffffffu, ss, o);
    ((__nv_bfloat162*)g_pb)[(size_t)w * (DDIM / 2) + lane] = __floats2bfloat162_rn(v.x, v.y);
    if (lane == 0) g_p2[w] = ss;
}

// ---------------------------------------------------------------------------
// Main: 128x128-tile bf16 mma.sync GEMM fused with masked min + loss.
// 512 threads, 16 warps as 8(m) x 2(n); warp tile 16x64 -> ~48 regs/thread,
// 2 CTAs/SM = 32 warps/SM for latency hiding.
// ---------------------------------------------------------------------------
__global__ __launch_bounds__(NTHREADS, 2) void glvq_main(
    const float* __restrict__ x, const int* __restrict__ y,
    const int* __restrict__ plab, float* __restrict__ out) {

    extern __shared__ char sm[];
    const uint32_t smb = (uint32_t)__cvta_generic_to_shared(sm);
    float* red  = (float*)(sm + SM_RED);
    float* xs2  = (float*)(sm + SM_XS2);
    float* rsum = (float*)(sm + SM_RSUM);
    int*   flag = (int*)(sm + SM_FLAG);

    const int tid = threadIdx.x;
    const int warp = tid >> 5, lane = tid & 31;
    const int wm = warp >> 1, wn = warp & 1;       // 8 m-groups x 2 n-halves
    const int qid = lane >> 2, qtr = lane & 3;
    const int rowBase = blockIdx.x * BM;

    // Issue B0 tile + tile-0 metadata via cp.async (overlaps x convert).
    {
        #pragma unroll
        for (int i = 0; i < 2; i++) {
            int c = tid + i * NTHREADS;
            cp16(smb + SM_B0 + padoff(c), (const char*)g_pb + (size_t)c * 16);
        }
        if (tid < 32)      cp16(smb + SM_PP2 + tid * 16, (const char*)g_p2 + tid * 16);
        else if (tid < 64) cp16(smb + SM_PPL + (tid - 32) * 16,
                                (const char*)plab + (tid - 32) * 16);
        CP_COMMIT();
    }

    // Convert this CTA's x tile fp32->bf16 into SM_AB1; row norms.
    // 512 threads: 4 threads per row, 16 floats each.
    {
        const int r = tid >> 2, q = tid & 3;
        const float4* xs4 = (const float4*)(x + (size_t)(rowBase + r) * DDIM + q * 16);
        float ss = 0.f;
        #pragma unroll
        for (int i = 0; i < 4; i++) {
            float4 v = xs4[i];
            ss += v.x * v.x + v.y * v.y + v.z * v.z + v.w * v.w;
            uint2 w;
            w.x = pk2(v.x, v.y); w.y = pk2(v.z, v.w);
            *(uint2*)(sm + SM_AB1 + r * ROWB + q * 32 + i * 8) = w;
        }
        ss += __shfl_xor_sync(0xffffffffu, ss, 1);
        ss += __shfl_xor_sync(0xffffffffu, ss, 2);
        if (q == 0) xs2[r] = ss;
    }

    // Row labels for this thread's two accumulator rows.
    int yv[2];
    #pragma unroll
    for (int h = 0; h < 2; h++)
        yv[h] = y[rowBase + wm * 16 + h * 8 + qid];

    float pmin[2] = {1e30f, 1e30f}, nmin[2] = {1e30f, 1e30f};

    __syncthreads();   // A tile (STS) + xs2 visible

    // Hoist A fragments (loop-invariant): 4x ldmatrix.x4 (16 regs).
    uint32_t a[4][4];
    {
        int arow = (lane & 7) + ((lane >> 3) & 1) * 8;
        int acol = (lane >> 4) * 8;
        #pragma unroll
        for (int kk = 0; kk < 4; kk++) {
            uint32_t ad = smb + SM_AB1
                + (uint32_t)(wm * 16 + arow) * ROWB
                + (uint32_t)(kk * 16 + acol) * 2;
            LDSMX4(a[kk], ad);
        }
    }
    __syncthreads();   // A reads done: SM_AB1 becomes B buffer 1.

    const uint32_t brow_off = (uint32_t)(lane & 7) * ROWB + (uint32_t)((lane >> 3) & 3) * 16;

    for (int t = 0; t < NTILES; t++) {
        CP_WAIT(0);        // B[t] + meta[t] resident
        __syncthreads();   // visible to all; B[t-1] buffer free

        // Prefetch B[t+1] + meta[t+1] into the other buffer.
        if (t + 1 < NTILES) {
            const char* src = (const char*)(g_pb + (size_t)(t + 1) * BN * DDIM);
            uint32_t dstb = smb + (((t + 1) & 1) ? SM_AB1 : SM_B0);
            #pragma unroll
            for (int i = 0; i < 2; i++) {
                int c = tid + i * NTHREADS;
                cp16(dstb + padoff(c), src + (size_t)c * 16);
            }
            uint32_t mb = ((t + 1) & 1) * 512;
            if (tid < 32)
                cp16(smb + SM_PP2 + mb + tid * 16,
                     (const char*)(g_p2 + (size_t)(t + 1) * BN) + tid * 16);
            else if (tid < 64)
                cp16(smb + SM_PPL + mb + (tid - 32) * 16,
                     (const char*)(plab + (size_t)(t + 1) * BN) + (tid - 32) * 16);
            CP_COMMIT();
        }

        const int buf = t & 1;
        const uint32_t pbase = smb + (buf ? SM_AB1 : SM_B0)
                             + (uint32_t)(wn * 64) * ROWB + brow_off;
        const float* pp2 = (const float*)(sm + SM_PP2 + buf * 512);
        const int*   ppl = (const int*)(sm + SM_PPL + buf * 512);

        #pragma unroll
        for (int nf = 0; nf < 8; nf++) {
            uint32_t b[8];
            uint32_t r0 = pbase + (uint32_t)(nf * 8) * ROWB;
            LDSMX4(b,     r0);
            LDSMX4(b + 4, r0 + 64);

            float c[4] = {0.f, 0.f, 0.f, 0.f};
            #pragma unroll
            for (int kk = 0; kk < 4; kk++)
                MMA16816(c, a[kk], b[kk * 2], b[kk * 2 + 1]);

            // Fused epilogue: s = p2 - 2*dot, masked running mins.
            const int jc = wn * 64 + nf * 8 + qtr * 2;
            float2 pp = *(const float2*)(pp2 + jc);
            int2   ll = *(const int2*)(ppl + jc);

            float s0 = fmaf(-2.f, c[0], pp.x);
            float s1 = fmaf(-2.f, c[1], pp.y);
            float s2 = fmaf(-2.f, c[2], pp.x);
            float s3 = fmaf(-2.f, c[3], pp.y);

            if (ll.x == yv[0]) pmin[0] = fminf(pmin[0], s0);
            else               nmin[0] = fminf(nmin[0], s0);
            if (ll.y == yv[0]) pmin[0] = fminf(pmin[0], s1);
            else               nmin[0] = fminf(nmin[0], s1);
            if (ll.x == yv[1]) pmin[1] = fminf(pmin[1], s2);
            else               nmin[1] = fminf(nmin[1], s2);
            if (ll.y == yv[1]) pmin[1] = fminf(pmin[1], s3);
            else               nmin[1] = fminf(nmin[1], s3);
        }
    }

    // Quad reduction (same rows, different cols across 4 lanes).
    #pragma unroll
    for (int h = 0; h < 2; h++) {
        #pragma unroll
        for (int o = 1; o <= 2; o <<= 1) {
            pmin[h] = fminf(pmin[h], __shfl_xor_sync(0xffffffffu, pmin[h], o));
            nmin[h] = fminf(nmin[h], __shfl_xor_sync(0xffffffffu, nmin[h], o));
        }
    }
    __syncthreads();
    if (qtr == 0) {
        #pragma unroll
        for (int h = 0; h < 2; h++) {
            int r = wm * 16 + h * 8 + qid;
            red[(wn * 2 + 0) * BM + r] = pmin[h];
            red[(wn * 2 + 1) * BM + r] = nmin[h];
        }
    }
    __syncthreads();

    float mysum = 0.f;
    if (tid < BM) {
        float spos = fminf(red[0 * BM + tid], red[2 * BM + tid]);
        float sneg = fminf(red[1 * BM + tid], red[3 * BM + tid]);
        float x2 = xs2[tid];
        float pos = sqrtf(fmaxf(spos + x2, 0.f));
        float neg = sqrtf(fmaxf(sneg + x2, 0.f));
        float mu = (pos - neg) / (pos + neg);
        mysum = 1.f / (1.f + expf(-mu));
    }
    #pragma unroll
    for (int o = 16; o; o >>= 1) mysum += __shfl_xor_sync(0xffffffffu, mysum, o);
    if (lane == 0) rsum[warp] = mysum;
    __syncthreads();
    if (tid == 0) {
        float s = 0.f;
        #pragma unroll
        for (int i = 0; i < 16; i++) s += rsum[i];
        g_partial[blockIdx.x] = s;
        __threadfence();
        unsigned int ticket = atomicAdd(&g_count, 1);
        *flag = (ticket == gridDim.x - 1) ? 1 : 0;
    }
    __syncthreads();

    if (*flag) {   // last block: deterministic final mean
        float s = 0.f;
        for (int i = tid; i < NBLOCKS; i += NTHREADS) s += __ldcg(&g_partial[i]);
        #pragma unroll
        for (int o = 16; o; o >>= 1) s += __shfl_xor_sync(0xffffffffu, s, o);
        if (lane == 0) rsum[warp] = s;
        __syncthreads();
        if (tid == 0) {
            float tot = 0.f;
            #pragma unroll
            for (int i = 0; i < 16; i++) tot += rsum[i];
            out[0] = tot * (1.0f / (float)NPTS);
            g_count = 0;   // reset for next graph replay
        }
    }
}

extern "C" void kernel_launch(void* const* d_in, const int* in_sizes, int n_in,
                              void* d_out, int out_size) {
    const float* x    = (const float*)d_in[0];
    const int*   yy   = (const int*)d_in[1];
    const float* prot = (const float*)d_in[2];
    const int*   plab = (const int*)d_in[3];
    float* out = (float*)d_out;

    cudaFuncSetAttribute(glvq_main, cudaFuncAttributeMaxDynamicSharedMemorySize, SM_TOTAL);

    prep_proto<<<PPTS / 8, 256>>>(prot);
    glvq_main<<<NBLOCKS, NTHREADS, SM_TOTAL>>>(x, yy, plab, out);
}

// round 10
// speedup vs baseline: 1.0676x; 1.0676x over previous
#include <cuda_runtime.h>
#include <cuda_fp16.h>
#include <math.h>
#include <stdint.h>

// Shape (fixed by dataset): N=65536, P=2048, D=64, 10 classes.
#define NPTS 65536
#define PPTS 2048
#define DDIM 64
#define BM 128
#define BN 128
#define LDSS 72              // fp16 per smem row (64 + 8 pad): conflict-free ldmatrix
#define ROWB (LDSS * 2)      // 144 bytes per padded row
#define NTILES (PPTS / BN)   // 16
#define NBLOCKS (NPTS / BM)  // 512

// __device__ scratch (allocation-free rule). Only prototypes staged.
__device__ __align__(16) __half g_pb[PPTS * DDIM];
__device__ __align__(16) float g_p2[PPTS];
__device__ float g_partial[NBLOCKS];
__device__ unsigned int g_count;   // zero-init; last block resets

// Dynamic smem layout (bytes)
#define SM_B0    0                 // B tile buffer (even t)         18432
#define SM_AB1   18432             // A tile, then B buffer (odd t)  18432
#define SM_PP2   36864             // 2 bufs x 128 f32                1024
#define SM_PPL   37888             // 2 bufs x 128 i32                1024
#define SM_RED   38912             // [2 wn][2][128] f32              4096
#define SM_XS2   43008             // 128 f32 row norms                512
#define SM_RSUM  43520             // 8 f32
#define SM_FLAG  43552
#define SM_TOTAL 43584

__device__ __forceinline__ void cp16(uint32_t dst, const void* src) {
    asm volatile("cp.async.cg.shared.global [%0], [%1], 16;\n" :: "r"(dst), "l"(src));
}
#define CP_COMMIT() asm volatile("cp.async.commit_group;\n" ::: "memory")
#define CP_WAIT(n)  asm volatile("cp.async.wait_group %0;\n" :: "n"(n) : "memory")

__device__ __forceinline__ uint32_t padoff(int idx) {     // idx-th 16B chunk
    return (uint32_t)((idx >> 3) * ROWB + (idx & 7) * 16);
}
__device__ __forceinline__ uint32_t pkh2(float a, float b) {
    __half2 t = __float22half2_rn(make_float2(a, b));
    return *(uint32_t*)&t;
}
#define LDSMX4(rr, addr) asm volatile( \
    "ldmatrix.sync.aligned.m8n8.x4.shared.b16 {%0,%1,%2,%3}, [%4];\n" \
    : "=r"((rr)[0]), "=r"((rr)[1]), "=r"((rr)[2]), "=r"((rr)[3]) : "r"(addr))
// fp16-in, fp16-accumulate HMMA (full-rate fallback path).
#define MMAF16(cc, aa, b0, b1) asm volatile( \
    "mma.sync.aligned.m16n8k16.row.col.f16.f16.f16.f16 " \
    "{%0,%1}, {%2,%3,%4,%5}, {%6,%7}, {%0,%1};\n" \
    : "+r"((cc)[0]), "+r"((cc)[1]) \
    : "r"((aa)[0]), "r"((aa)[1]), "r"((aa)[2]), "r"((aa)[3]), "r"(b0), "r"(b1))

// ---------------------------------------------------------------------------
// Prep (prototypes only): fp32 rows -> fp16 rows + row sum-of-squares.
// ---------------------------------------------------------------------------
__global__ void prep_proto(const float* __restrict__ p) {
    int w = (blockIdx.x * blockDim.x + threadIdx.x) >> 5;
    int lane = threadIdx.x & 31;
    if (w >= PPTS) return;
    float2 v = ((const float2*)(p + (size_t)w * DDIM))[lane];
    float ss = v.x * v.x + v.y * v.y;
    #pragma unroll
    for (int o = 16; o; o >>= 1) ss += __shfl_xor_sync(0xffffffffu, ss, o);
    ((__half2*)g_pb)[(size_t)w * (DDIM / 2) + lane] = __float22half2_rn(make_float2(v.x, v.y));
    if (lane == 0) g_p2[w] = ss;
}

// ---------------------------------------------------------------------------
// Main: 128x128-tile fp16 mma.sync GEMM (f16 accumulate, split-K into two
// chains merged by HADD2) fused with masked min + loss. 256 threads,
// 8 warps = 4(m) x 2(n), 3 CTAs/SM.
// ---------------------------------------------------------------------------
__global__ __launch_bounds__(256, 3) void glvq_main(
    const float* __restrict__ x, const int* __restrict__ y,
    const int* __restrict__ plab, float* __restrict__ out) {

    extern __shared__ char sm[];
    const uint32_t smb = (uint32_t)__cvta_generic_to_shared(sm);
    float* red  = (float*)(sm + SM_RED);
    float* xs2  = (float*)(sm + SM_XS2);
    float* rsum = (float*)(sm + SM_RSUM);
    int*   flag = (int*)(sm + SM_FLAG);

    const int tid = threadIdx.x;
    const int warp = tid >> 5, lane = tid & 31;
    const int wm = warp >> 1, wn = warp & 1;
    const int qid = lane >> 2, qtr = lane & 3;
    const int rowBase = blockIdx.x * BM;

    // Issue B0 tile + tile-0 metadata via cp.async (overlaps x convert).
    {
        #pragma unroll
        for (int i = 0; i < 4; i++) {
            int c = tid + i * 256;
            cp16(smb + SM_B0 + padoff(c), (const char*)g_pb + (size_t)c * 16);
        }
        if (tid < 32)      cp16(smb + SM_PP2 + tid * 16, (const char*)g_p2 + tid * 16);
        else if (tid < 64) cp16(smb + SM_PPL + (tid - 32) * 16,
                                (const char*)plab + (tid - 32) * 16);
        CP_COMMIT();
    }

    // Convert this CTA's x tile fp32->fp16 into SM_AB1; row norms.
    {
        const int r = tid >> 1, h = tid & 1;
        const float4* xs4 = (const float4*)(x + (size_t)(rowBase + r) * DDIM + h * 32);
        float ss = 0.f;
        #pragma unroll
        for (int i = 0; i < 4; i++) {
            float4 v0 = xs4[i * 2], v1 = xs4[i * 2 + 1];
            ss += v0.x * v0.x + v0.y * v0.y + v0.z * v0.z + v0.w * v0.w
                + v1.x * v1.x + v1.y * v1.y + v1.z * v1.z + v1.w * v1.w;
            uint4 w;
            w.x = pkh2(v0.x, v0.y); w.y = pkh2(v0.z, v0.w);
            w.z = pkh2(v1.x, v1.y); w.w = pkh2(v1.z, v1.w);
            *(uint4*)(sm + SM_AB1 + r * ROWB + h * 64 + i * 16) = w;
        }
        ss += __shfl_xor_sync(0xffffffffu, ss, 1);
        if (h == 0) xs2[r] = ss;
    }

    // Row labels for this thread's accumulator rows.
    int yv[2][2];
    #pragma unroll
    for (int mf = 0; mf < 2; mf++)
        #pragma unroll
        for (int h = 0; h < 2; h++)
            yv[mf][h] = y[rowBase + wm * 32 + mf * 16 + h * 8 + qid];

    float pmin[2][2], nmin[2][2];
    #pragma unroll
    for (int mf = 0; mf < 2; mf++)
        #pragma unroll
        for (int h = 0; h < 2; h++) { pmin[mf][h] = 1e30f; nmin[mf][h] = 1e30f; }

    __syncthreads();   // A tile (STS) + xs2 visible

    // Hoist A fragments (loop-invariant): 8x ldmatrix.x4 from SM_AB1.
    uint32_t a[2][4][4];
    {
        int arow = (lane & 7) + ((lane >> 3) & 1) * 8;
        int acol = (lane >> 4) * 8;
        #pragma unroll
        for (int mf = 0; mf < 2; mf++)
            #pragma unroll
            for (int kk = 0; kk < 4; kk++) {
                uint32_t ad = smb + SM_AB1
                    + (uint32_t)(wm * 32 + mf * 16 + arow) * ROWB
                    + (uint32_t)(kk * 16 + acol) * 2;
                LDSMX4(a[mf][kk], ad);
            }
    }
    __syncthreads();   // A reads done: SM_AB1 becomes B buffer 1.

    const uint32_t brow_off = (uint32_t)(lane & 7) * ROWB + (uint32_t)((lane >> 3) & 3) * 16;

    for (int t = 0; t < NTILES; t++) {
        CP_WAIT(0);        // B[t] + meta[t] resident
        __syncthreads();   // visible to all; B[t-1] buffer free

        // Prefetch B[t+1] + meta[t+1] into the other buffer.
        if (t + 1 < NTILES) {
            const char* src = (const char*)(g_pb + (size_t)(t + 1) * BN * DDIM);
            uint32_t dstb = smb + (((t + 1) & 1) ? SM_AB1 : SM_B0);
            #pragma unroll
            for (int i = 0; i < 4; i++) {
                int c = tid + i * 256;
                cp16(dstb + padoff(c), src + (size_t)c * 16);
            }
            uint32_t mb = ((t + 1) & 1) * 512;
            if (tid < 32)
                cp16(smb + SM_PP2 + mb + tid * 16,
                     (const char*)(g_p2 + (size_t)(t + 1) * BN) + tid * 16);
            else if (tid < 64)
                cp16(smb + SM_PPL + mb + (tid - 32) * 16,
                     (const char*)(plab + (size_t)(t + 1) * BN) + (tid - 32) * 16);
            CP_COMMIT();
        }

        const int buf = t & 1;
        const uint32_t pbase = smb + (buf ? SM_AB1 : SM_B0)
                             + (uint32_t)(wn * 64) * ROWB + brow_off;
        const float* pp2 = (const float*)(sm + SM_PP2 + buf * 512);
        const int*   ppl = (const int*)(sm + SM_PPL + buf * 512);

        #pragma unroll
        for (int nf = 0; nf < 8; nf++) {
            uint32_t b[8];
            uint32_t r0 = pbase + (uint32_t)(nf * 8) * ROWB;
            LDSMX4(b,     r0);
            LDSMX4(b + 4, r0 + 64);

            // 4 independent f16-acc chains (split-K: kk{0,1} and kk{2,3}).
            uint32_t cA0[2] = {0, 0}, cB0[2] = {0, 0};
            uint32_t cA1[2] = {0, 0}, cB1[2] = {0, 0};
            MMAF16(cA0, a[0][0], b[0], b[1]);
            MMAF16(cB0, a[0][2], b[4], b[5]);
            MMAF16(cA1, a[1][0], b[0], b[1]);
            MMAF16(cB1, a[1][2], b[4], b[5]);
            MMAF16(cA0, a[0][1], b[2], b[3]);
            MMAF16(cB0, a[0][3], b[6], b[7]);
            MMAF16(cA1, a[1][1], b[2], b[3]);
            MMAF16(cB1, a[1][3], b[6], b[7]);

            // Merge chains (HADD2) and unpack to f32.
            __half2 d00 = __hadd2(*(__half2*)&cA0[0], *(__half2*)&cB0[0]);
            __half2 d01 = __hadd2(*(__half2*)&cA0[1], *(__half2*)&cB0[1]);
            __half2 d10 = __hadd2(*(__half2*)&cA1[0], *(__half2*)&cB1[0]);
            __half2 d11 = __hadd2(*(__half2*)&cA1[1], *(__half2*)&cB1[1]);
            float2 f00 = __half22float2(d00);   // mf0, row qid
            float2 f01 = __half22float2(d01);   // mf0, row qid+8
            float2 f10 = __half22float2(d10);   // mf1, row qid
            float2 f11 = __half22float2(d11);   // mf1, row qid+8

            // Fused epilogue: s = p2 - 2*dot, masked running mins.
            const int jc = wn * 64 + nf * 8 + qtr * 2;
            float2 pp = *(const float2*)(pp2 + jc);
            int2   ll = *(const int2*)(ppl + jc);

            float s00 = fmaf(-2.f, f00.x, pp.x);
            float s01 = fmaf(-2.f, f00.y, pp.y);
            float s02 = fmaf(-2.f, f01.x, pp.x);
            float s03 = fmaf(-2.f, f01.y, pp.y);
            float s10 = fmaf(-2.f, f10.x, pp.x);
            float s11 = fmaf(-2.f, f10.y, pp.y);
            float s12 = fmaf(-2.f, f11.x, pp.x);
            float s13 = fmaf(-2.f, f11.y, pp.y);

            if (ll.x == yv[0][0]) pmin[0][0] = fminf(pmin[0][0], s00);
            else                  nmin[0][0] = fminf(nmin[0][0], s00);
            if (ll.y == yv[0][0]) pmin[0][0] = fminf(pmin[0][0], s01);
            else                  nmin[0][0] = fminf(nmin[0][0], s01);
            if (ll.x == yv[0][1]) pmin[0][1] = fminf(pmin[0][1], s02);
            else                  nmin[0][1] = fminf(nmin[0][1], s02);
            if (ll.y == yv[0][1]) pmin[0][1] = fminf(pmin[0][1], s03);
            else                  nmin[0][1] = fminf(nmin[0][1], s03);
            if (ll.x == yv[1][0]) pmin[1][0] = fminf(pmin[1][0], s10);
            else                  nmin[1][0] = fminf(nmin[1][0], s10);
            if (ll.y == yv[1][0]) pmin[1][0] = fminf(pmin[1][0], s11);
            else                  nmin[1][0] = fminf(nmin[1][0], s11);
            if (ll.x == yv[1][1]) pmin[1][1] = fminf(pmin[1][1], s12);
            else                  nmin[1][1] = fminf(nmin[1][1], s12);
            if (ll.y == yv[1][1]) pmin[1][1] = fminf(pmin[1][1], s13);
            else                  nmin[1][1] = fminf(nmin[1][1], s13);
        }
    }

    // Quad reduction (same rows, different cols across 4 lanes).
    #pragma unroll
    for (int mf = 0; mf < 2; mf++)
        #pragma unroll
        for (int h = 0; h < 2; h++) {
            #pragma unroll
            for (int o = 1; o <= 2; o <<= 1) {
                pmin[mf][h] = fminf(pmin[mf][h], __shfl_xor_sync(0xffffffffu, pmin[mf][h], o));
                nmin[mf][h] = fminf(nmin[mf][h], __shfl_xor_sync(0xffffffffu, nmin[mf][h], o));
            }
        }
    __syncthreads();
    if (qtr == 0) {
        #pragma unroll
        for (int mf = 0; mf < 2; mf++)
            #pragma unroll
            for (int h = 0; h < 2; h++) {
                int r = wm * 32 + mf * 16 + h * 8 + qid;
                red[(wn * 2 + 0) * BM + r] = pmin[mf][h];
                red[(wn * 2 + 1) * BM + r] = nmin[mf][h];
            }
    }
    __syncthreads();

    float mysum = 0.f;
    if (tid < BM) {
        float spos = fminf(red[0 * BM + tid], red[2 * BM + tid]);
        float sneg = fminf(red[1 * BM + tid], red[3 * BM + tid]);
        float x2 = xs2[tid];
        float pos = sqrtf(fmaxf(spos + x2, 0.f));
        float neg = sqrtf(fmaxf(sneg + x2, 0.f));
        float mu = (pos - neg) / (pos + neg);
        mysum = 1.f / (1.f + expf(-mu));
    }
    #pragma unroll
    for (int o = 16; o; o >>= 1) mysum += __shfl_xor_sync(0xffffffffu, mysum, o);
    if (lane == 0) rsum[warp] = mysum;
    __syncthreads();
    if (tid == 0) {
        float s = 0.f;
        #pragma unroll
        for (int i = 0; i < 8; i++) s += rsum[i];
        g_partial[blockIdx.x] = s;
        __threadfence();
        unsigned int ticket = atomicAdd(&g_count, 1);
        *flag = (ticket == gridDim.x - 1) ? 1 : 0;
    }
    __syncthreads();

    if (*flag) {   // last block: deterministic final mean
        float s = 0.f;
        for (int i = tid; i < NBLOCKS; i += 256) s += __ldcg(&g_partial[i]);
        #pragma unroll
        for (int o = 16; o; o >>= 1) s += __shfl_xor_sync(0xffffffffu, s, o);
        if (lane == 0) rsum[warp] = s;
        __syncthreads();
        if (tid == 0) {
            float tot = 0.f;
            #pragma unroll
            for (int i = 0; i < 8; i++) tot += rsum[i];
            out[0] = tot * (1.0f / (float)NPTS);
            g_count = 0;   // reset for next graph replay
        }
    }
}

extern "C" void kernel_launch(void* const* d_in, const int* in_sizes, int n_in,
                              void* d_out, int out_size) {
    const float* x    = (const float*)d_in[0];
    const int*   yy   = (const int*)d_in[1];
    const float* prot = (const float*)d_in[2];
    const int*   plab = (const int*)d_in[3];
    float* out = (float*)d_out;

    cudaFuncSetAttribute(glvq_main, cudaFuncAttributeMaxDynamicSharedMemorySize, SM_TOTAL);

    prep_proto<<<PPTS / 8, 256>>>(prot);
    glvq_main<<<NBLOCKS, 256, SM_TOTAL>>>(x, yy, plab, out);
}

// round 11
// speedup vs baseline: 1.1292x; 1.0577x over previous
#include <cuda_runtime.h>
#include <cuda_bf16.h>
#include <math.h>
#include <stdint.h>

// Shape (fixed by dataset): N=65536, P=2048, D=64, 10 classes.
#define NPTS 65536
#define PPTS 2048
#define DDIM 64
#define BM 256               // two 128-row x-tiles per CTA
#define BN 128
#define LDSS 72              // bf16 per smem row (64 + 8 pad): conflict-free ldmatrix
#define ROWB (LDSS * 2)      // 144 bytes per padded row
#define NTILES (PPTS / BN)   // 16
#define NBLOCKS (NPTS / BM)  // 256

// __device__ scratch (allocation-free rule). Only prototypes staged.
__device__ __align__(16) __nv_bfloat16 g_pb[PPTS * DDIM];
__device__ __align__(16) float g_p2[PPTS];
__device__ float g_partial[NBLOCKS];
__device__ unsigned int g_count;   // zero-init; last block resets

// Dynamic smem layout (bytes)
#define SM_B0    0                 // B tile buffer (even t)          18432
#define SM_AB1   18432             // x-convert staging, then B buf   18432
#define SM_PP2   36864             // 2 bufs x 128 f32                 1024
#define SM_PPL   37888             // 2 bufs x 128 i32                 1024
#define SM_RED   38912             // [2 wn][2][256] f32               8192
#define SM_XS2   47104             // 256 f32 row norms                1024
#define SM_RSUM  48128             // 8 f32
#define SM_FLAG  48160
#define SM_TOTAL 48192

__device__ __forceinline__ void cp16(uint32_t dst, const void* src) {
    asm volatile("cp.async.cg.shared.global [%0], [%1], 16;\n" :: "r"(dst), "l"(src));
}
#define CP_COMMIT() asm volatile("cp.async.commit_group;\n" ::: "memory")
#define CP_WAIT(n)  asm volatile("cp.async.wait_group %0;\n" :: "n"(n) : "memory")

__device__ __forceinline__ uint32_t padoff(int idx) {     // idx-th 16B chunk
    return (uint32_t)((idx >> 3) * ROWB + (idx & 7) * 16);
}
__device__ __forceinline__ uint32_t pk2(float a, float b) {
    __nv_bfloat162 t = __floats2bfloat162_rn(a, b);
    return *(uint32_t*)&t;
}
#define LDSMX4(rr, addr) asm volatile( \
    "ldmatrix.sync.aligned.m8n8.x4.shared.b16 {%0,%1,%2,%3}, [%4];\n" \
    : "=r"((rr)[0]), "=r"((rr)[1]), "=r"((rr)[2]), "=r"((rr)[3]) : "r"(addr))
#define MMA16816(cc, aa, b0, b1) asm volatile( \
    "mma.sync.aligned.m16n8k16.row.col.f32.bf16.bf16.f32 " \
    "{%0,%1,%2,%3}, {%4,%5,%6,%7}, {%8,%9}, {%0,%1,%2,%3};\n" \
    : "+f"((cc)[0]), "+f"((cc)[1]), "+f"((cc)[2]), "+f"((cc)[3]) \
    : "r"((aa)[0]), "r"((aa)[1]), "r"((aa)[2]), "r"((aa)[3]), "r"(b0), "r"(b1))

// ---------------------------------------------------------------------------
// Prep (prototypes only): fp32 rows -> bf16 rows + row sum-of-squares.
// ---------------------------------------------------------------------------
__global__ void prep_proto(const float* __restrict__ p) {
    int w = (blockIdx.x * blockDim.x + threadIdx.x) >> 5;
    int lane = threadIdx.x & 31;
    if (w >= PPTS) return;
    float2 v = ((const float2*)(p + (size_t)w * DDIM))[lane];
    float ss = v.x * v.x + v.y * v.y;
    #pragma unroll
    for (int o = 16; o; o >>= 1) ss += __shfl_xor_sync(0xffffffffu, ss, o);
    ((__nv_bfloat162*)g_pb)[(size_t)w * (DDIM / 2) + lane] = __floats2bfloat162_rn(v.x, v.y);
    if (lane == 0) g_p2[w] = ss;
}

// ---------------------------------------------------------------------------
// Main: 256x128-tile bf16 mma.sync GEMM fused with masked min + loss.
// 8 warps = 4(m) x 2(n); warp tile 64x64 (4 m-frags) -> every B fragment
// feeds 2x the MMAs of the 128-row variant; 4 independent MMA chains per
// slab; barriers per FLOP halved. 2 CTAs/SM, grid 256 (single wave).
// ---------------------------------------------------------------------------
__global__ __launch_bounds__(256, 2) void glvq_main(
    const float* __restrict__ x, const int* __restrict__ y,
    const int* __restrict__ plab, float* __restrict__ out) {

    extern __shared__ char sm[];
    const uint32_t smb = (uint32_t)__cvta_generic_to_shared(sm);
    float* red  = (float*)(sm + SM_RED);
    float* xs2  = (float*)(sm + SM_XS2);
    float* rsum = (float*)(sm + SM_RSUM);
    int*   flag = (int*)(sm + SM_FLAG);

    const int tid = threadIdx.x;
    const int warp = tid >> 5, lane = tid & 31;
    const int wm = warp >> 1, wn = warp & 1;   // 4 m-warps x 2 n-halves
    const int qid = lane >> 2, qtr = lane & 3;
    const int rowBase = blockIdx.x * BM;

    // Issue B0 tile + tile-0 metadata via cp.async (overlaps x converts).
    {
        #pragma unroll
        for (int i = 0; i < 4; i++) {
            int c = tid + i * 256;
            cp16(smb + SM_B0 + padoff(c), (const char*)g_pb + (size_t)c * 16);
        }
        if (tid < 32)      cp16(smb + SM_PP2 + tid * 16, (const char*)g_p2 + tid * 16);
        else if (tid < 64) cp16(smb + SM_PPL + (tid - 32) * 16,
                                (const char*)plab + (tid - 32) * 16);
        CP_COMMIT();
    }

    // A fragments for this warp's 64 rows: a[4 mf][4 kk][4] (64 regs).
    uint32_t a[4][4][4];
    const int arow = (lane & 7) + ((lane >> 3) & 1) * 8;
    const int acol = (lane >> 4) * 8;

    // Two staging passes through SM_AB1: rows [0,128) then [128,256).
    #pragma unroll
    for (int stage = 0; stage < 2; stage++) {
        // Convert 128 rows fp32->bf16 into SM_AB1; row norms.
        const int r = tid >> 1, h = tid & 1;
        const float4* xs4 = (const float4*)(
            x + (size_t)(rowBase + stage * 128 + r) * DDIM + h * 32);
        float ss = 0.f;
        #pragma unroll
        for (int i = 0; i < 4; i++) {
            float4 v0 = xs4[i * 2], v1 = xs4[i * 2 + 1];
            ss += v0.x * v0.x + v0.y * v0.y + v0.z * v0.z + v0.w * v0.w
                + v1.x * v1.x + v1.y * v1.y + v1.z * v1.z + v1.w * v1.w;
            uint4 w;
            w.x = pk2(v0.x, v0.y); w.y = pk2(v0.z, v0.w);
            w.z = pk2(v1.x, v1.y); w.w = pk2(v1.z, v1.w);
            *(uint4*)(sm + SM_AB1 + r * ROWB + h * 64 + i * 16) = w;
        }
        ss += __shfl_xor_sync(0xffffffffu, ss, 1);
        if (h == 0) xs2[stage * 128 + r] = ss;
        __syncthreads();   // staged tile visible

        // Warps whose 64 rows live in this stage hoist their A fragments.
        if ((wm >> 1) == stage) {
            const int lrow = (wm & 1) * 64;   // row within the staged 128
            #pragma unroll
            for (int mf = 0; mf < 4; mf++)
                #pragma unroll
                for (int kk = 0; kk < 4; kk++) {
                    uint32_t ad = smb + SM_AB1
                        + (uint32_t)(lrow + mf * 16 + arow) * ROWB
                        + (uint32_t)(kk * 16 + acol) * 2;
                    LDSMX4(a[mf][kk], ad);
                }
        }
        __syncthreads();   // A reads done before buffer reuse
    }

    // Row labels for this thread's 8 accumulator rows.
    int yv[4][2];
    #pragma unroll
    for (int mf = 0; mf < 4; mf++)
        #pragma unroll
        for (int h = 0; h < 2; h++)
            yv[mf][h] = y[rowBase + wm * 64 + mf * 16 + h * 8 + qid];

    float pmin[4][2], nmin[4][2];
    #pragma unroll
    for (int mf = 0; mf < 4; mf++)
        #pragma unroll
        for (int h = 0; h < 2; h++) { pmin[mf][h] = 1e30f; nmin[mf][h] = 1e30f; }

    const uint32_t brow_off = (uint32_t)(lane & 7) * ROWB + (uint32_t)((lane >> 3) & 3) * 16;

    for (int t = 0; t < NTILES; t++) {
        CP_WAIT(0);        // B[t] + meta[t] resident
        __syncthreads();   // visible to all; B[t-1] buffer free

        // Prefetch B[t+1] + meta[t+1] into the other buffer.
        if (t + 1 < NTILES) {
            const char* src = (const char*)(g_pb + (size_t)(t + 1) * BN * DDIM);
            uint32_t dstb = smb + (((t + 1) & 1) ? SM_AB1 : SM_B0);
            #pragma unroll
            for (int i = 0; i < 4; i++) {
                int c = tid + i * 256;
                cp16(dstb + padoff(c), src + (size_t)c * 16);
            }
            uint32_t mb = ((t + 1) & 1) * 512;
            if (tid < 32)
                cp16(smb + SM_PP2 + mb + tid * 16,
                     (const char*)(g_p2 + (size_t)(t + 1) * BN) + tid * 16);
            else if (tid < 64)
                cp16(smb + SM_PPL + mb + (tid - 32) * 16,
                     (const char*)(plab + (size_t)(t + 1) * BN) + (tid - 32) * 16);
            CP_COMMIT();
        }

        const int buf = t & 1;
        const uint32_t pbase = smb + (buf ? SM_AB1 : SM_B0)
                             + (uint32_t)(wn * 64) * ROWB + brow_off;
        const float* pp2 = (const float*)(sm + SM_PP2 + buf * 512);
        const int*   ppl = (const int*)(sm + SM_PPL + buf * 512);

        #pragma unroll
        for (int nf = 0; nf < 8; nf++) {
            uint32_t b[8];
            uint32_t r0 = pbase + (uint32_t)(nf * 8) * ROWB;
            LDSMX4(b,     r0);
            LDSMX4(b + 4, r0 + 64);

            // 4 independent MMA chains (one per mf), each depth 4.
            float c0[4] = {0.f, 0.f, 0.f, 0.f};
            float c1[4] = {0.f, 0.f, 0.f, 0.f};
            float c2[4] = {0.f, 0.f, 0.f, 0.f};
            float c3[4] = {0.f, 0.f, 0.f, 0.f};
            #pragma unroll
            for (int kk = 0; kk < 4; kk++) {
                MMA16816(c0, a[0][kk], b[kk * 2], b[kk * 2 + 1]);
                MMA16816(c1, a[1][kk], b[kk * 2], b[kk * 2 + 1]);
                MMA16816(c2, a[2][kk], b[kk * 2], b[kk * 2 + 1]);
                MMA16816(c3, a[3][kk], b[kk * 2], b[kk * 2 + 1]);
            }

            // Fused epilogue: s = p2 - 2*dot, masked running mins.
            const int jc = wn * 64 + nf * 8 + qtr * 2;
            float2 pp = *(const float2*)(pp2 + jc);
            int2   ll = *(const int2*)(ppl + jc);

            float* cs[4] = {c0, c1, c2, c3};
            #pragma unroll
            for (int mf = 0; mf < 4; mf++) {
                float s0 = fmaf(-2.f, cs[mf][0], pp.x);
                float s1 = fmaf(-2.f, cs[mf][1], pp.y);
                float s2 = fmaf(-2.f, cs[mf][2], pp.x);
                float s3 = fmaf(-2.f, cs[mf][3], pp.y);
                if (ll.x == yv[mf][0]) pmin[mf][0] = fminf(pmin[mf][0], s0);
                else                   nmin[mf][0] = fminf(nmin[mf][0], s0);
                if (ll.y == yv[mf][0]) pmin[mf][0] = fminf(pmin[mf][0], s1);
                else                   nmin[mf][0] = fminf(nmin[mf][0], s1);
                if (ll.x == yv[mf][1]) pmin[mf][1] = fminf(pmin[mf][1], s2);
                else                   nmin[mf][1] = fminf(nmin[mf][1], s2);
                if (ll.y == yv[mf][1]) pmin[mf][1] = fminf(pmin[mf][1], s3);
                else                   nmin[mf][1] = fminf(nmin[mf][1], s3);
            }
        }
    }

    // Quad reduction (same rows, different cols across 4 lanes).
    #pragma unroll
    for (int mf = 0; mf < 4; mf++)
        #pragma unroll
        for (int h = 0; h < 2; h++) {
            #pragma unroll
            for (int o = 1; o <= 2; o <<= 1) {
                pmin[mf][h] = fminf(pmin[mf][h], __shfl_xor_sync(0xffffffffu, pmin[mf][h], o));
                nmin[mf][h] = fminf(nmin[mf][h], __shfl_xor_sync(0xffffffffu, nmin[mf][h], o));
            }
        }
    __syncthreads();
    if (qtr == 0) {
        #pragma unroll
        for (int mf = 0; mf < 4; mf++)
            #pragma unroll
            for (int h = 0; h < 2; h++) {
                int r = wm * 64 + mf * 16 + h * 8 + qid;
                red[(wn * 2 + 0) * BM + r] = pmin[mf][h];
                red[(wn * 2 + 1) * BM + r] = nmin[mf][h];
            }
    }
    __syncthreads();

    // 256 rows, 256 threads: one per row.
    float spos = fminf(red[0 * BM + tid], red[2 * BM + tid]);
    float sneg = fminf(red[1 * BM + tid], red[3 * BM + tid]);
    float x2 = xs2[tid];
    float pos = sqrtf(fmaxf(spos + x2, 0.f));
    float neg = sqrtf(fmaxf(sneg + x2, 0.f));
    float mu = (pos - neg) / (pos + neg);
    float mysum = 1.f / (1.f + expf(-mu));
    #pragma unroll
    for (int o = 16; o; o >>= 1) mysum += __shfl_xor_sync(0xffffffffu, mysum, o);
    if (lane == 0) rsum[warp] = mysum;
    __syncthreads();
    if (tid == 0) {
        float s = 0.f;
        #pragma unroll
        for (int i = 0; i < 8; i++) s += rsum[i];
        g_partial[blockIdx.x] = s;
        __threadfence();
        unsigned int ticket = atomicAdd(&g_count, 1);
        *flag = (ticket == gridDim.x - 1) ? 1 : 0;
    }
    __syncthreads();

    if (*flag) {   // last block: deterministic final mean
        float s = __ldcg(&g_partial[tid]);   // NBLOCKS == blockDim.x == 256
        #pragma unroll
        for (int o = 16; o; o >>= 1) s += __shfl_xor_sync(0xffffffffu, s, o);
        if (lane == 0) rsum[warp] = s;
        __syncthreads();
        if (tid == 0) {
            float tot = 0.f;
            #pragma unroll
            for (int i = 0; i < 8; i++) tot += rsum[i];
            out[0] = tot * (1.0f / (float)NPTS);
            g_count = 0;   // reset for next graph replay
        }
    }
}

extern "C" void kernel_launch(void* const* d_in, const int* in_sizes, int n_in,
                              void* d_out, int out_size) {
    const float* x    = (const float*)d_in[0];
    const int*   yy   = (const int*)d_in[1];
    const float* prot = (const float*)d_in[2];
    const int*   plab = (const int*)d_in[3];
    float* out = (float*)d_out;

    cudaFuncSetAttribute(glvq_main, cudaFuncAttributeMaxDynamicSharedMemorySize, SM_TOTAL);

    prep_proto<<<PPTS / 8, 256>>>(prot);
    glvq_main<<<NBLOCKS, 256, SM_TOTAL>>>(x, yy, plab, out);
}